// round 17
// baseline (speedup 1.0000x reference)
#include <cuda_runtime.h>

// Problem constants
#define Bn   64
#define Cn   256
#define Tn   64
#define Vn   25
#define Hn   512
#define TVn  1600      // T*V
#define CTVn 409600    // C*T*V

typedef unsigned long long u64;

// ---------------- packed f32x2 helpers (Blackwell 2x fp32 path) ----------------
__device__ __forceinline__ u64 f2fma(u64 a, u64 b, u64 c){
    u64 d; asm("fma.rn.f32x2 %0,%1,%2,%3;" : "=l"(d) : "l"(a), "l"(b), "l"(c)); return d;
}
__device__ __forceinline__ u64 f2add(u64 a, u64 b){
    u64 d; asm("add.rn.f32x2 %0,%1,%2;" : "=l"(d) : "l"(a), "l"(b)); return d;
}
__device__ __forceinline__ u64 f2pack(float x, float y){
    u64 d; asm("mov.b64 %0,{%1,%2};" : "=l"(d) : "f"(x), "f"(y)); return d;
}
__device__ __forceinline__ float2 f2unpack(u64 a){
    float2 r; asm("mov.b64 {%0,%1},%2;" : "=f"(r.x), "=f"(r.y) : "l"(a)); return r;
}

// fast tanh: 1 MUFU.EX2 + fast divide; err ~1e-6 rel
__device__ __forceinline__ float ftanh(float x){
    float ax = fabsf(x);
    float e  = __expf(ax + ax);
    float r  = __fdividef(e - 1.0f, e + 1.0f);
    r = (ax > 20.0f) ? 1.0f : r;
    return copysignf(r, x);
}

// Intermediate u = tanh(z W1 + b1), PADDED layout [B][H][28]
__device__ float g_U[Bn * Hn * 28];

// load 7 x ulonglong2 (one padded row: 28 floats) from SMEM — warp-broadcast
__device__ __forceinline__ void ldz(ulonglong2* q, const u64* row){
    const ulonglong2* p = (const ulonglong2*)row;
    #pragma unroll
    for (int j = 0; j < 7; j++) q[j] = p[j];
}

// 13 packed FMAs into acc[0..12] for one output column
__device__ __forceinline__ void fma13(u64* acc, const ulonglong2* q, float wv){
    u64 wp = f2pack(wv, wv);
    acc[0]  = f2fma(q[0].x, wp, acc[0]);
    acc[1]  = f2fma(q[0].y, wp, acc[1]);
    acc[2]  = f2fma(q[1].x, wp, acc[2]);
    acc[3]  = f2fma(q[1].y, wp, acc[3]);
    acc[4]  = f2fma(q[2].x, wp, acc[4]);
    acc[5]  = f2fma(q[2].y, wp, acc[5]);
    acc[6]  = f2fma(q[3].x, wp, acc[6]);
    acc[7]  = f2fma(q[3].y, wp, acc[7]);
    acc[8]  = f2fma(q[4].x, wp, acc[8]);
    acc[9]  = f2fma(q[4].y, wp, acc[9]);
    acc[10] = f2fma(q[5].x, wp, acc[10]);
    acc[11] = f2fma(q[5].y, wp, acc[11]);
    acc[12] = f2fma(q[6].x, wp, acc[12]);
}

// 4 output columns share one z row: 52 FMA2 per 7 LDS.128
__device__ __forceinline__ void fma52(u64* acc, const ulonglong2* q, float4 wv){
    fma13(acc,      q, wv.x);
    fma13(acc + 13, q, wv.y);
    fma13(acc + 26, q, wv.z);
    fma13(acc + 39, q, wv.w);
}

// Software-pipelined 64-row K reduction, 4 output columns per thread.
// zrow: padded SMEM rows (14 u64); rows 0..63 consumed, row 64 addressable.
// w: float4 weight stream (4 adjacent output columns), ws4 = row stride in float4.
__device__ __forceinline__ void kloop64(u64* acc, const u64* zrow,
                                        const float4* w, int ws4){
    float4 wbuf[4];
    #pragma unroll
    for (int i = 0; i < 4; i++) wbuf[i] = w[(size_t)i * ws4];

    ulonglong2 zA[7], zB[7];
    ldz(zA, zrow);

    #pragma unroll 1
    for (int c0 = 0; c0 < 64; c0 += 4){
        float4 wn[4];
        #pragma unroll
        for (int i = 0; i < 4; i++){
            int cn = c0 + 4 + i;
            wn[i] = (cn < 64) ? w[(size_t)cn * ws4] : make_float4(0.f,0.f,0.f,0.f);
        }
        ldz(zB, zrow + (size_t)(c0 + 1) * 14);
        fma52(acc, zA, wbuf[0]);
        ldz(zA, zrow + (size_t)(c0 + 2) * 14);
        fma52(acc, zB, wbuf[1]);
        ldz(zB, zrow + (size_t)(c0 + 3) * 14);
        fma52(acc, zA, wbuf[2]);
        ldz(zA, zrow + (size_t)(c0 + 4) * 14);
        fma52(acc, zB, wbuf[3]);
        #pragma unroll
        for (int i = 0; i < 4; i++) wbuf[i] = wn[i];
    }
}

// ---------------- init: out[:,:,0,:] = h[:,:,0,:] ----------------
__global__ void kinit(const float* __restrict__ h, float* __restrict__ out){
    int idx = blockIdx.x * 256 + threadIdx.x;
    if (idx >= Bn * Cn * Vn) return;
    int v  = idx % Vn;
    int bc = idx / Vn;
    size_t a = (size_t)bc * TVn + v;
    out[a] = h[a];
}

// ---------------- K1: U[b,h,:] = tanh( sum_c z_t[b,c,:] * W1[c,h] + b1[h] ) ----
// grid (4 hblocks, 32 batch-pairs), 256 thr:
//   hg = tid&31 (4-h group), bs = (tid>>5)&1 (batch in pair), ks = tid>>6 (K quarter)
// SMEM: z tiles [2][257][14] u64 (57568 B) + partials [2][32][4][52] u64 (106496 B)
__global__ void __launch_bounds__(256, 1) k1(
    const float* __restrict__ hp, const float* __restrict__ outp,
    const float* __restrict__ W1, const float* __restrict__ b1,
    const float* __restrict__ tf, int t)
{
    extern __shared__ u64 zs[];
    u64* comb = zs + 2 * 257 * 14;   // [bs][hg][ks][52]

    int tid = threadIdx.x;
    int bp  = blockIdx.y;
    int hb  = blockIdx.x;

    // stage z_t for two batches (teacher-forcing select folded in);
    // pad lanes garbage-tolerant (only feed discarded accumulators)
    #pragma unroll
    for (int s = 0; s < 2; s++){
        int b = bp * 2 + s;
        float r = tf[t * Bn + b];
        const float* src = (r < 0.5f ? outp : hp) + (size_t)b * CTVn + (size_t)t * Vn;
        float* dst = (float*)(zs + (size_t)s * 257 * 14);
        for (int i = tid; i < 256 * Vn; i += 256){
            int c = i / Vn;
            int v = i - c * Vn;
            dst[c * 28 + v] = src[(size_t)c * TVn + v];
        }
    }
    __syncthreads();

    int hg = tid & 31;
    int bs = (tid >> 5) & 1;
    int ks = tid >> 6;
    int hidx = hb * 128 + hg * 4;

    u64 acc[52];
    #pragma unroll
    for (int r = 0; r < 52; r++) acc[r] = 0ull;

    kloop64(acc,
            zs + (size_t)bs * 257 * 14 + (size_t)ks * 64 * 14,
            (const float4*)W1 + (size_t)(ks * 64) * (Hn / 4) + (hidx >> 2),
            Hn / 4);

    // all 4 K-slices publish partials
    {
        u64* cp = comb + ((size_t)((bs * 32 + hg) * 4 + ks)) * 52;
        #pragma unroll
        for (int r = 0; r < 52; r++) cp[r] = acc[r];
    }
    __syncthreads();

    // parallel epilogue: thread (bs,hg,ks) finalizes column h = hidx + ks
    {
        const u64* base = comb + ((size_t)(bs * 32 + hg) * 4) * 52 + ks * 13;
        int hx = hidx + ks;
        float bias = b1[hx];
        u64 bpk = f2pack(bias, bias);
        float vals[28];
        #pragma unroll
        for (int r = 0; r < 13; r++){
            u64 s = f2add(f2add(base[r], base[52 + r]),
                          f2add(base[104 + r], f2add(base[156 + r], bpk)));
            float2 xy = f2unpack(s);
            vals[2 * r]     = ftanh(xy.x);
            vals[2 * r + 1] = ftanh(xy.y);
        }
        vals[26] = 0.f; vals[27] = 0.f;
        float* up = g_U + ((size_t)(bp * 2 + bs) * Hn + hx) * 28;
        #pragma unroll
        for (int j = 0; j < 7; j++)
            ((float4*)up)[j] = make_float4(vals[4*j], vals[4*j+1], vals[4*j+2], vals[4*j+3]);
    }
}

// ---------------- K2: out[b,c,t+1,:] = z_t[b,c,:] + b2[c] + sum_h U[b,h,:]*W2[h,c]
// grid (2 cblocks, 64 batches), 256 thr:
//   cg = tid&31 (4-c group), ks = tid>>5 (K eighth, 64 h rows each)
// SMEM: U tile [514][14] u64 (57568 B) + partials [32][8][52] u64 (106496 B)
__global__ void __launch_bounds__(256, 1) k2(
    const float* __restrict__ hp, float* __restrict__ outp,
    const float* __restrict__ W2, const float* __restrict__ b2,
    const float* __restrict__ tf, int t)
{
    extern __shared__ u64 smem[];
    u64* su   = smem;             // [514][14]
    u64* comb = smem + 514 * 14;  // [cg][ks][52]

    int tid = threadIdx.x;
    int b   = blockIdx.y;
    int cb  = blockIdx.x;

    // stage padded U[b] (straight float4 copy — identical layout)
    {
        const float4* src = (const float4*)(g_U + (size_t)b * Hn * 28);
        float4* dst = (float4*)su;
        #pragma unroll
        for (int j = 0; j < 14; j++)
            dst[tid + j * 256] = src[tid + j * 256];
    }
    __syncthreads();

    int cg = tid & 31;
    int ks = tid >> 5;            // 0..7
    int cidx = cb * 128 + cg * 4;

    u64 acc[52];
    #pragma unroll
    for (int r = 0; r < 52; r++) acc[r] = 0ull;

    kloop64(acc,
            su + (size_t)(ks * 64) * 14,
            (const float4*)W2 + (size_t)(ks * 64) * (Cn / 4) + (cidx >> 2),
            Cn / 4);

    // all 8 K-slices publish partials
    {
        u64* cp = comb + ((size_t)(cg * 8 + ks)) * 52;
        #pragma unroll
        for (int r = 0; r < 52; r++) cp[r] = acc[r];
    }
    __syncthreads();

    // parallel epilogue: threads ks=0..3 finalize column c = cidx + ks
    if (ks < 4){
        const u64* base = comb + (size_t)(cg * 8) * 52 + ks * 13;
        int cx = cidx + ks;
        float bb = b2[cx];
        u64 bpk = f2pack(bb, bb);
        float r = tf[t * Bn + b];
        const float* zsrc = (r < 0.5f ? (const float*)outp : hp)
                            + (size_t)b * CTVn + (size_t)cx * TVn + (size_t)t * Vn;
        float* dst = outp + (size_t)b * CTVn + (size_t)cx * TVn + (size_t)(t + 1) * Vn;
        #pragma unroll
        for (int rr = 0; rr < 13; rr++){
            u64 s = f2add(
                f2add(f2add(base[rr],        base[52 + rr]),
                      f2add(base[104 + rr],  base[156 + rr])),
                f2add(f2add(base[208 + rr],  base[260 + rr]),
                      f2add(base[312 + rr],  f2add(base[364 + rr], bpk))));
            float2 a = f2unpack(s);
            int v = rr * 2;
            dst[v] = zsrc[v] + a.x;
            if (v + 1 < Vn) dst[v + 1] = zsrc[v + 1] + a.y;
        }
    }
}

// ---------------- launch ----------------
extern "C" void kernel_launch(void* const* d_in, const int* in_sizes, int n_in,
                              void* d_out, int out_size)
{
    (void)in_sizes; (void)n_in; (void)out_size;
    const float* h  = (const float*)d_in[0];
    const float* W1 = (const float*)d_in[1];
    const float* b1 = (const float*)d_in[2];
    const float* W2 = (const float*)d_in[3];
    const float* b2 = (const float*)d_in[4];
    const float* tf = (const float*)d_in[5];
    float* out = (float*)d_out;

    const int SM1 = (2 * 257 * 14 + 2 * 32 * 4 * 52) * 8;   // 164064
    const int SM2 = (514 * 14 + 32 * 8 * 52) * 8;           // 164064
    cudaFuncSetAttribute(k1, cudaFuncAttributeMaxDynamicSharedMemorySize, SM1);
    cudaFuncSetAttribute(k2, cudaFuncAttributeMaxDynamicSharedMemorySize, SM2);

    kinit<<<(Bn * Cn * Vn + 255) / 256, 256>>>(h, out);
    for (int t = 0; t < Tn - 1; t++){
        k1<<<dim3(4, 32), 256, SM1>>>(h, out, W1, b1, tf, t);
        k2<<<dim3(2, 64), 256, SM2>>>(h, out, W2, b2, tf, t);
    }
}